// round 1
// baseline (speedup 1.0000x reference)
#include <cuda_runtime.h>
#include <cuda_bf16.h>
#include <math.h>

#define NB  2
#define NT  2048
#define ND  2048
#define NH  16
#define NKV 8
#define DHD 128
#define NG  2

// Scratch (no allocations allowed): ~100 MB of device .bss
__device__ float g_q[(size_t)NB * NH * NT * DHD];
__device__ float g_k[(size_t)NB * NKV * NT * DHD];
__device__ float g_v[(size_t)NB * NKV * NT * DHD];
__device__ float g_ctx[(size_t)NB * NT * NH * DHD];

// ---------------------------------------------------------------------------
// Tiled SGEMM: C = A @ W^T.  A: [M,K] row-major, W: [N,K] row-major.
// BM=BN=128, BK=16, 256 threads, 8x8 per thread.
// HEAD_MAJOR: write C[(b*heads + n/128)*NT + t][n%128]  (b=m/NT, t=m%NT)
// else:       write C[m*N + n]
// ---------------------------------------------------------------------------
template <bool HEAD_MAJOR>
__global__ void __launch_bounds__(256) gemm_kernel(
    const float* __restrict__ A, const float* __restrict__ W,
    float* __restrict__ C, int M, int N, int K, int heads)
{
    __shared__ float As[16][128];
    __shared__ float Ws[16][128];

    const int tid = threadIdx.x;
    const int m0 = blockIdx.y * 128;
    const int n0 = blockIdx.x * 128;
    const int tx = tid & 15;
    const int ty = tid >> 4;
    const int lrow = tid >> 1;          // 0..127
    const int lk = (tid & 1) * 4;       // 0 or 4

    const float* Ap = A + (size_t)(m0 + lrow) * K + lk;
    const float* Wp = W + (size_t)(n0 + lrow) * K + lk;

    float acc[8][8];
#pragma unroll
    for (int i = 0; i < 8; i++)
#pragma unroll
        for (int j = 0; j < 8; j++) acc[i][j] = 0.0f;

    for (int k0 = 0; k0 < K; k0 += 16) {
        float4 a0 = *(const float4*)(Ap + k0);
        float4 a1 = *(const float4*)(Ap + k0 + 8);
        float4 w0 = *(const float4*)(Wp + k0);
        float4 w1 = *(const float4*)(Wp + k0 + 8);
        __syncthreads();
        As[lk + 0][lrow] = a0.x; As[lk + 1][lrow] = a0.y;
        As[lk + 2][lrow] = a0.z; As[lk + 3][lrow] = a0.w;
        As[lk + 8][lrow] = a1.x; As[lk + 9][lrow] = a1.y;
        As[lk + 10][lrow] = a1.z; As[lk + 11][lrow] = a1.w;
        Ws[lk + 0][lrow] = w0.x; Ws[lk + 1][lrow] = w0.y;
        Ws[lk + 2][lrow] = w0.z; Ws[lk + 3][lrow] = w0.w;
        Ws[lk + 8][lrow] = w1.x; Ws[lk + 9][lrow] = w1.y;
        Ws[lk + 10][lrow] = w1.z; Ws[lk + 11][lrow] = w1.w;
        __syncthreads();
#pragma unroll
        for (int kk = 0; kk < 16; kk++) {
            float a[8], b[8];
            *(float4*)(a)     = *(const float4*)&As[kk][ty * 8];
            *(float4*)(a + 4) = *(const float4*)&As[kk][ty * 8 + 4];
            *(float4*)(b)     = *(const float4*)&Ws[kk][tx * 8];
            *(float4*)(b + 4) = *(const float4*)&Ws[kk][tx * 8 + 4];
#pragma unroll
            for (int i = 0; i < 8; i++)
#pragma unroll
                for (int j = 0; j < 8; j++) acc[i][j] += a[i] * b[j];
        }
    }

#pragma unroll
    for (int i = 0; i < 8; i++) {
        const int m = m0 + ty * 8 + i;
        const int bb = m / NT;
        const int t = m % NT;
#pragma unroll
        for (int j = 0; j < 8; j++) {
            const int n = n0 + tx * 8 + j;
            if (HEAD_MAJOR) {
                const int h = n >> 7;
                const int dh = n & 127;
                C[(((size_t)bb * heads + h) * NT + t) * DHD + dh] = acc[i][j];
            } else {
                C[(size_t)m * N + n] = acc[i][j];
            }
        }
    }
}

// ---------------------------------------------------------------------------
// Fused RMSNorm (over DH=128) + RoPE (half-split). One block per head-row.
// buf layout: [..., T, 128]; row % T gives position t.
// ---------------------------------------------------------------------------
__global__ void __launch_bounds__(128) normrope_kernel(
    float* __restrict__ buf, const float* __restrict__ w)
{
    const int row = blockIdx.x;
    const int t = row & (NT - 1);
    float* p = buf + (size_t)row * DHD;
    const int d = threadIdx.x;

    float v = p[d];
    float ss = v * v;
#pragma unroll
    for (int o = 16; o > 0; o >>= 1) ss += __shfl_xor_sync(0xffffffffu, ss, o);

    __shared__ float sred[4];
    __shared__ float sh[128];
    if ((d & 31) == 0) sred[d >> 5] = ss;
    __syncthreads();
    const float tot = sred[0] + sred[1] + sred[2] + sred[3];
    const float xn = v * rsqrtf(tot * (1.0f / 128.0f) + 1e-6f) * w[d];
    sh[d] = xn;
    __syncthreads();

    const int fi = d & 63;
    // inv_freq = 1e6^(-fi/64), computed in double for faithful fp32 rounding
    const float invf = (float)exp(-(double)fi * (13.815510557964274 / 64.0));
    const float arg = (float)t * invf;
    float s, c;
    sincosf(arg, &s, &c);
    const float pr = sh[d ^ 64];
    p[d] = (d < 64) ? (xn * c - pr * s) : (xn * c + pr * s);
}

// ---------------------------------------------------------------------------
// Flash attention, fp32, causal, GQA (kv head = q head / 2).
// 64 query rows x 64 key cols per tile, DH=128. 256 threads (16x16),
// each thread: 4x4 of S, 4x8 of O.
// ---------------------------------------------------------------------------
#define ATTN_SMEM ((64 * 128 * 3 + 64 * 65) * 4)

__global__ void __launch_bounds__(256) attn_kernel()
{
    extern __shared__ float sm[];
    float* Qs = sm;                    // [128][64]  (k-major)
    float* Ks = sm + 128 * 64;         // [128][64]  (k-major)
    float* Vs = sm + 2 * 128 * 64;     // [64][128]  (row-major)
    float* Ps = sm + 3 * 128 * 64;     // [64][65]   (padded)

    const int bh = blockIdx.y;
    const int b = bh >> 4;
    const int hq = bh & 15;
    const int hk = hq >> 1;
    const int q0 = blockIdx.x * 64;

    const float* Qg = g_q + (((size_t)b * NH + hq) * NT + q0) * DHD;
    const float* Kg = g_k + ((size_t)b * NKV + hk) * NT * DHD;
    const float* Vg = g_v + ((size_t)b * NKV + hk) * NT * DHD;

    const int tid = threadIdx.x;
    const int tx = tid & 15;
    const int ty = tid >> 4;

    // Load Q tile transposed: Qs[k][r]
    for (int i = tid; i < 2048; i += 256) {
        const int r = i & 63;
        const int kg = (i >> 6) << 2;
        float4 qv = *(const float4*)(Qg + (size_t)r * DHD + kg);
        Qs[(kg + 0) * 64 + r] = qv.x;
        Qs[(kg + 1) * 64 + r] = qv.y;
        Qs[(kg + 2) * 64 + r] = qv.z;
        Qs[(kg + 3) * 64 + r] = qv.w;
    }

    float m_i[4], l_i[4], o[4][8];
#pragma unroll
    for (int i = 0; i < 4; i++) {
        m_i[i] = -1e30f;
        l_i[i] = 0.0f;
#pragma unroll
        for (int j = 0; j < 8; j++) o[i][j] = 0.0f;
    }

    const float scale = 0.08838834764831845f;  // 1/sqrt(128)
    const int ntiles = (q0 >> 6) + 1;

    for (int jt = 0; jt < ntiles; jt++) {
        const int k0 = jt * 64;
        __syncthreads();  // prev PV done (and Q stores on first iter)

        // K transposed
        for (int i = tid; i < 2048; i += 256) {
            const int r = i & 63;
            const int kg = (i >> 6) << 2;
            float4 kv = *(const float4*)(Kg + (size_t)(k0 + r) * DHD + kg);
            Ks[(kg + 0) * 64 + r] = kv.x;
            Ks[(kg + 1) * 64 + r] = kv.y;
            Ks[(kg + 2) * 64 + r] = kv.z;
            Ks[(kg + 3) * 64 + r] = kv.w;
        }
        // V row-major
        for (int i = tid; i < 2048; i += 256) {
            const int r = i >> 5;
            const int kg = (i & 31) << 2;
            *(float4*)&Vs[r * 128 + kg] =
                *(const float4*)(Vg + (size_t)(k0 + r) * DHD + kg);
        }
        __syncthreads();

        // S = Q K^T (4x4 per thread)
        float s[4][4];
#pragma unroll
        for (int i = 0; i < 4; i++)
#pragma unroll
            for (int j = 0; j < 4; j++) s[i][j] = 0.0f;

        for (int k = 0; k < 128; k++) {
            float4 aq = *(const float4*)&Qs[k * 64 + ty * 4];
            float4 bk = *(const float4*)&Ks[k * 64 + tx * 4];
            const float a[4] = {aq.x, aq.y, aq.z, aq.w};
            const float bb2[4] = {bk.x, bk.y, bk.z, bk.w};
#pragma unroll
            for (int i = 0; i < 4; i++)
#pragma unroll
                for (int j = 0; j < 4; j++) s[i][j] += a[i] * bb2[j];
        }

        // scale + causal mask
#pragma unroll
        for (int i = 0; i < 4; i++) {
            const int qr = q0 + ty * 4 + i;
#pragma unroll
            for (int j = 0; j < 4; j++) {
                const int kc = k0 + tx * 4 + j;
                s[i][j] = (kc <= qr) ? s[i][j] * scale : -1e30f;
            }
        }

        // online softmax per row (replicated across the 16 tx lanes)
#pragma unroll
        for (int i = 0; i < 4; i++) {
            float rm = fmaxf(fmaxf(s[i][0], s[i][1]), fmaxf(s[i][2], s[i][3]));
#pragma unroll
            for (int off = 8; off > 0; off >>= 1)
                rm = fmaxf(rm, __shfl_xor_sync(0xffffffffu, rm, off));
            const float mn = fmaxf(m_i[i], rm);
            const float alpha = __expf(m_i[i] - mn);
            float rs = 0.0f;
#pragma unroll
            for (int j = 0; j < 4; j++) {
                const float pv = __expf(s[i][j] - mn);
                s[i][j] = pv;
                rs += pv;
            }
#pragma unroll
            for (int off = 8; off > 0; off >>= 1)
                rs += __shfl_xor_sync(0xffffffffu, rs, off);
            l_i[i] = l_i[i] * alpha + rs;
            m_i[i] = mn;
#pragma unroll
            for (int j = 0; j < 8; j++) o[i][j] *= alpha;
#pragma unroll
            for (int j = 0; j < 4; j++)
                Ps[(ty * 4 + i) * 65 + tx * 4 + j] = s[i][j];
        }
        __syncthreads();

        // O += P @ V
        for (int c = 0; c < 64; c++) {
            float pr[4];
#pragma unroll
            for (int i = 0; i < 4; i++) pr[i] = Ps[(ty * 4 + i) * 65 + c];
            float4 v0 = *(const float4*)&Vs[c * 128 + tx * 8];
            float4 v1 = *(const float4*)&Vs[c * 128 + tx * 8 + 4];
            const float vv[8] = {v0.x, v0.y, v0.z, v0.w, v1.x, v1.y, v1.z, v1.w};
#pragma unroll
            for (int i = 0; i < 4; i++)
#pragma unroll
                for (int j = 0; j < 8; j++) o[i][j] += pr[i] * vv[j];
        }
    }

    // write ctx[b][t][hq*128 + d]
#pragma unroll
    for (int i = 0; i < 4; i++) {
        const int r = q0 + ty * 4 + i;
        const float inv = 1.0f / l_i[i];
        float* dst = g_ctx + ((size_t)b * NT + r) * (NH * DHD) + hq * DHD + tx * 8;
#pragma unroll
        for (int j = 0; j < 8; j++) dst[j] = o[i][j] * inv;
    }
}

// ---------------------------------------------------------------------------
extern "C" void kernel_launch(void* const* d_in, const int* in_sizes, int n_in,
                              void* d_out, int out_size)
{
    const float* x   = (const float*)d_in[0];
    const float* wq  = (const float*)d_in[1];
    const float* wk  = (const float*)d_in[2];
    const float* wv  = (const float*)d_in[3];
    const float* wo  = (const float*)d_in[4];
    const float* qnw = (const float*)d_in[5];
    const float* knw = (const float*)d_in[6];
    float* out = (float*)d_out;

    float *qp, *kp, *vp, *cp;
    cudaGetSymbolAddress((void**)&qp, g_q);
    cudaGetSymbolAddress((void**)&kp, g_k);
    cudaGetSymbolAddress((void**)&vp, g_v);
    cudaGetSymbolAddress((void**)&cp, g_ctx);

    cudaFuncSetAttribute(attn_kernel,
                         cudaFuncAttributeMaxDynamicSharedMemorySize, ATTN_SMEM);

    const int M = NB * NT;  // 4096

    gemm_kernel<true><<<dim3((NH * DHD) / 128, M / 128), 256>>>(
        x, wq, qp, M, NH * DHD, ND, NH);
    gemm_kernel<true><<<dim3((NKV * DHD) / 128, M / 128), 256>>>(
        x, wk, kp, M, NKV * DHD, ND, NKV);
    gemm_kernel<true><<<dim3((NKV * DHD) / 128, M / 128), 256>>>(
        x, wv, vp, M, NKV * DHD, ND, NKV);

    normrope_kernel<<<NB * NH * NT, 128>>>(qp, qnw);
    normrope_kernel<<<NB * NKV * NT, 128>>>(kp, knw);

    attn_kernel<<<dim3(NT / 64, NB * NH), 256, ATTN_SMEM>>>();

    gemm_kernel<false><<<dim3(ND / 128, M / 128), 256>>>(
        cp, wo, out, M, ND, ND, 0);
}

// round 4
// speedup vs baseline: 1.8435x; 1.8435x over previous
#include <cuda_runtime.h>
#include <cuda_bf16.h>
#include <math.h>
#include <stdint.h>

#define NB  2
#define NT  2048
#define ND  2048
#define NH  16
#define NKV 8
#define DHD 128

// ---------------- device scratch (no allocations allowed) ----------------
__device__ float g_q[(size_t)NB * NH * NT * DHD];
__device__ float g_k[(size_t)NB * NKV * NT * DHD];
__device__ float g_v[(size_t)NB * NKV * NT * DHD];
__device__ float g_ctx[(size_t)NB * NT * NH * DHD];
__device__ float g_cos[NT * 64];
__device__ float g_sin[NT * 64];

__device__ __nv_bfloat16 g_xh[(size_t)NB * NT * ND];
__device__ __nv_bfloat16 g_xl[(size_t)NB * NT * ND];
__device__ __nv_bfloat16 g_wqh[(size_t)NH * DHD * ND];
__device__ __nv_bfloat16 g_wql[(size_t)NH * DHD * ND];
__device__ __nv_bfloat16 g_wkh[(size_t)NKV * DHD * ND];
__device__ __nv_bfloat16 g_wkl[(size_t)NKV * DHD * ND];
__device__ __nv_bfloat16 g_wvh[(size_t)NKV * DHD * ND];
__device__ __nv_bfloat16 g_wvl[(size_t)NKV * DHD * ND];
__device__ __nv_bfloat16 g_woh[(size_t)ND * NH * DHD];
__device__ __nv_bfloat16 g_wol[(size_t)ND * NH * DHD];
__device__ __nv_bfloat16 g_ch[(size_t)NB * NT * NH * DHD];
__device__ __nv_bfloat16 g_cl[(size_t)NB * NT * NH * DHD];

// ---------------- PTX helpers (base-target ISA only) ----------------
__device__ __forceinline__ uint32_t smem_u32(const void* p) {
    uint32_t a;
    asm("{ .reg .u64 t; cvta.to.shared.u64 t, %1; cvt.u32.u64 %0, t; }"
        : "=r"(a) : "l"(p));
    return a;
}
__device__ __forceinline__ void ldm_x4(uint32_t* r, uint32_t addr) {
    asm volatile("ldmatrix.sync.aligned.m8n8.x4.shared.b16 {%0,%1,%2,%3}, [%4];"
                 : "=r"(r[0]), "=r"(r[1]), "=r"(r[2]), "=r"(r[3]) : "r"(addr));
}
__device__ __forceinline__ void mma16816(float* c, const uint32_t* a, const uint32_t* b) {
    asm volatile(
        "mma.sync.aligned.m16n8k16.row.col.f32.bf16.bf16.f32 "
        "{%0,%1,%2,%3}, {%4,%5,%6,%7}, {%8,%9}, {%0,%1,%2,%3};"
        : "+f"(c[0]), "+f"(c[1]), "+f"(c[2]), "+f"(c[3])
        : "r"(a[0]), "r"(a[1]), "r"(a[2]), "r"(a[3]), "r"(b[0]), "r"(b[1]));
}
__device__ __forceinline__ void cpa16(uint32_t dst, const void* src) {
    asm volatile("cp.async.cg.shared.global [%0], [%1], 16;" :: "r"(dst), "l"(src));
}
__device__ __forceinline__ void cpa_commit() {
    asm volatile("cp.async.commit_group;" ::: "memory");
}
__device__ __forceinline__ void cpa_wait0() {
    asm volatile("cp.async.wait_group 0;" ::: "memory");
}

// ---------------- fp32 -> bf16 hi/lo split ----------------
__global__ void __launch_bounds__(256) split_kernel(
    const float* __restrict__ s, __nv_bfloat16* __restrict__ h,
    __nv_bfloat16* __restrict__ l, int n4)
{
    int i = blockIdx.x * 256 + threadIdx.x;
    if (i >= n4) return;
    float4 v = ((const float4*)s)[i];
    __nv_bfloat16 h0 = __float2bfloat16(v.x);
    __nv_bfloat16 h1 = __float2bfloat16(v.y);
    __nv_bfloat16 h2 = __float2bfloat16(v.z);
    __nv_bfloat16 h3 = __float2bfloat16(v.w);
    __nv_bfloat16 l0 = __float2bfloat16(v.x - __bfloat162float(h0));
    __nv_bfloat16 l1 = __float2bfloat16(v.y - __bfloat162float(h1));
    __nv_bfloat16 l2 = __float2bfloat16(v.z - __bfloat162float(h2));
    __nv_bfloat16 l3 = __float2bfloat16(v.w - __bfloat162float(h3));
    uint2 hp, lp;
    hp.x = (uint32_t)__bfloat16_as_ushort(h0) | ((uint32_t)__bfloat16_as_ushort(h1) << 16);
    hp.y = (uint32_t)__bfloat16_as_ushort(h2) | ((uint32_t)__bfloat16_as_ushort(h3) << 16);
    lp.x = (uint32_t)__bfloat16_as_ushort(l0) | ((uint32_t)__bfloat16_as_ushort(l1) << 16);
    lp.y = (uint32_t)__bfloat16_as_ushort(l2) | ((uint32_t)__bfloat16_as_ushort(l3) << 16);
    ((uint2*)h)[i] = hp;
    ((uint2*)l)[i] = lp;
}

// ---------------- HMMA bf16-split GEMM: C = A @ W^T ----------------
// A: [M,2048] row-major (hi/lo), W: [N,2048] row-major (hi/lo).
// Tile 128x128xBK32. 8 warps (2x4), each 64x32. 2-stage cp.async pipeline.
// SMEM tile: 128 rows x 32 bf16, padded row stride 40 elems (80 B).
#define GK       2048
#define ROWB     80          // bytes per smem row
#define TILEB    10240       // 128 * 80
#define STAGEB   40960       // 4 tiles (Ah, Al, Wh, Wl)
#define GSMEM    (2 * STAGEB)

__device__ __forceinline__ void load_chunk(
    uint32_t base, const __nv_bfloat16* const* srcs, int tid, int c)
{
#pragma unroll
    for (int t = 0; t < 4; t++) {
#pragma unroll
        for (int p = 0; p < 2; p++) {
            const int idx = tid + p * 256;
            const int row = idx >> 2;
            const int seg = idx & 3;
            cpa16(base + t * TILEB + row * ROWB + seg * 16,
                  srcs[t] + (size_t)row * GK + c * 32 + seg * 8);
        }
    }
    cpa_commit();
}

__device__ __forceinline__ void compute_chunk(
    uint32_t base, int wm, int wn, uint32_t a_off, uint32_t b_off,
    float acc[4][4][4])
{
#pragma unroll
    for (int kk = 0; kk < 2; kk++) {
        const uint32_t koff = kk * 32;  // 16 bf16 = 32 B
        const uint32_t paH = base + wm * 64 * ROWB + koff + a_off;
        const uint32_t pbH = base + 2 * TILEB + wn * 32 * ROWB + koff + b_off;

        uint32_t af[4][4], bf0[2][4], bf1[2][4];
#pragma unroll
        for (int i = 0; i < 4; i++) ldm_x4(af[i], paH + i * (16 * ROWB));
        ldm_x4(bf0[0], pbH);
        ldm_x4(bf0[1], pbH + 16 * ROWB);
        ldm_x4(bf1[0], pbH + TILEB);
        ldm_x4(bf1[1], pbH + TILEB + 16 * ROWB);

        // hi*hi
#pragma unroll
        for (int i = 0; i < 4; i++)
#pragma unroll
            for (int j = 0; j < 4; j++)
                mma16816(acc[i][j], af[i], &bf0[j >> 1][(j & 1) * 2]);
        // hi*lo
#pragma unroll
        for (int i = 0; i < 4; i++)
#pragma unroll
            for (int j = 0; j < 4; j++)
                mma16816(acc[i][j], af[i], &bf1[j >> 1][(j & 1) * 2]);
        // lo*hi
#pragma unroll
        for (int i = 0; i < 4; i++) ldm_x4(af[i], paH + TILEB + i * (16 * ROWB));
#pragma unroll
        for (int i = 0; i < 4; i++)
#pragma unroll
            for (int j = 0; j < 4; j++)
                mma16816(acc[i][j], af[i], &bf0[j >> 1][(j & 1) * 2]);
    }
}

template <bool HEAD_MAJOR>
__global__ void __launch_bounds__(256) gemm_hmma(
    const __nv_bfloat16* __restrict__ Ah, const __nv_bfloat16* __restrict__ Al,
    const __nv_bfloat16* __restrict__ Bh, const __nv_bfloat16* __restrict__ Bl,
    float* __restrict__ C, int N, int heads)
{
    extern __shared__ char smem[];
    const uint32_t sb = smem_u32(smem);
    const int tid = threadIdx.x;
    const int lane = tid & 31;
    const int w = tid >> 5;
    const int wm = w >> 2;
    const int wn = w & 3;
    const int m0 = blockIdx.y * 128;
    const int n0 = blockIdx.x * 128;

    const __nv_bfloat16* srcs[4] = {
        Ah + (size_t)m0 * GK, Al + (size_t)m0 * GK,
        Bh + (size_t)n0 * GK, Bl + (size_t)n0 * GK};

    // ldmatrix per-lane address offsets
    const uint32_t a_off = (uint32_t)(lane & 15) * ROWB + (uint32_t)(lane >> 4) * 16;
    const uint32_t b_off = (uint32_t)((lane & 7) + ((lane >> 4) << 3)) * ROWB +
                           (uint32_t)((lane >> 3) & 1) * 16;

    float acc[4][4][4];
#pragma unroll
    for (int i = 0; i < 4; i++)
#pragma unroll
        for (int j = 0; j < 4; j++)
#pragma unroll
            for (int r = 0; r < 4; r++) acc[i][j][r] = 0.0f;

    load_chunk(sb, srcs, tid, 0);

    const int nchunks = GK / 32;  // 64
    for (int c = 0; c < nchunks; c++) {
        cpa_wait0();
        __syncthreads();
        if (c + 1 < nchunks)
            load_chunk(sb + ((c + 1) & 1) * STAGEB, srcs, tid, c + 1);
        compute_chunk(sb + (c & 1) * STAGEB, wm, wn, a_off, b_off, acc);
    }

    // store: lane g = lane>>2 (row), tg = lane&3 (col pair)
    const int g = lane >> 2;
    const int tg = lane & 3;
#pragma unroll
    for (int i = 0; i < 4; i++) {
        const int mrow0 = m0 + wm * 64 + i * 16 + g;
#pragma unroll
        for (int j = 0; j < 4; j++) {
            const int col = wn * 32 + j * 8 + tg * 2;
#pragma unroll
            for (int h2 = 0; h2 < 2; h2++) {
                const int m = mrow0 + h2 * 8;
                const int b = m >> 11;
                const int t = m & (NT - 1);
                float2 v = {acc[i][j][h2 * 2], acc[i][j][h2 * 2 + 1]};
                if (HEAD_MAJOR) {
                    const int head = blockIdx.x;  // one head per 128-wide N tile
                    *(float2*)(C + (((size_t)b * heads + head) * NT + t) * DHD + col) = v;
                } else {
                    *(float2*)(C + (size_t)m * N + n0 + col) = v;
                }
            }
        }
    }
}

// ---------------- RoPE table ----------------
__global__ void rope_table_kernel() {
    const int t = blockIdx.x;
    const int fi = threadIdx.x;  // 0..63
    const float invf = (float)exp(-(double)fi * (13.815510557964274 / 64.0));
    const float arg = (float)t * invf;
    float s, c;
    sincosf(arg, &s, &c);
    g_cos[t * 64 + fi] = c;
    g_sin[t * 64 + fi] = s;
}

// ---------------- fused RMSNorm + RoPE, one warp per row ----------------
__global__ void __launch_bounds__(256) normrope_kernel(
    float* __restrict__ buf, const float* __restrict__ w)
{
    const int row = blockIdx.x * 8 + (threadIdx.x >> 5);
    const int lid = threadIdx.x & 31;
    const int t = row & (NT - 1);
    float* p = buf + (size_t)row * DHD + lid * 4;

    float4 v = *(float4*)p;
    float ss = v.x * v.x + v.y * v.y + v.z * v.z + v.w * v.w;
#pragma unroll
    for (int o = 16; o > 0; o >>= 1) ss += __shfl_xor_sync(0xffffffffu, ss, o);
    const float rn = rsqrtf(ss * (1.0f / 128.0f) + 1e-6f);

    float4 wv = *(const float4*)(w + lid * 4);
    float x0 = v.x * rn * wv.x, x1 = v.y * rn * wv.y;
    float x2 = v.z * rn * wv.z, x3 = v.w * rn * wv.w;

    const float p0 = __shfl_xor_sync(0xffffffffu, x0, 16);
    const float p1 = __shfl_xor_sync(0xffffffffu, x1, 16);
    const float p2 = __shfl_xor_sync(0xffffffffu, x2, 16);
    const float p3 = __shfl_xor_sync(0xffffffffu, x3, 16);

    const int fi0 = (lid & 15) * 4;
    float4 cv = *(const float4*)(g_cos + t * 64 + fi0);
    float4 sv = *(const float4*)(g_sin + t * 64 + fi0);
    const float sg = (lid < 16) ? -1.0f : 1.0f;

    float4 o;
    o.x = x0 * cv.x + sg * p0 * sv.x;
    o.y = x1 * cv.y + sg * p1 * sv.y;
    o.z = x2 * cv.z + sg * p2 * sv.z;
    o.w = x3 * cv.w + sg * p3 * sv.w;
    *(float4*)p = o;
}

// ---------------- flash attention, fp32, causal, GQA ----------------
#define ATTN_SMEM ((64 * 128 * 3 + 64 * 65) * 4)

__global__ void __launch_bounds__(256) attn_kernel()
{
    extern __shared__ float sm[];
    float* Qs = sm;
    float* Ks = sm + 128 * 64;
    float* Vs = sm + 2 * 128 * 64;
    float* Ps = sm + 3 * 128 * 64;

    const int bh = blockIdx.y;
    const int b = bh >> 4;
    const int hq = bh & 15;
    const int hk = hq >> 1;
    const int q0 = blockIdx.x * 64;

    const float* Qg = g_q + (((size_t)b * NH + hq) * NT + q0) * DHD;
    const float* Kg = g_k + ((size_t)b * NKV + hk) * NT * DHD;
    const float* Vg = g_v + ((size_t)b * NKV + hk) * NT * DHD;

    const int tid = threadIdx.x;
    const int tx = tid & 15;
    const int ty = tid >> 4;

    for (int i = tid; i < 2048; i += 256) {
        const int r = i & 63;
        const int kg = (i >> 6) << 2;
        float4 qv = *(const float4*)(Qg + (size_t)r * DHD + kg);
        Qs[(kg + 0) * 64 + r] = qv.x;
        Qs[(kg + 1) * 64 + r] = qv.y;
        Qs[(kg + 2) * 64 + r] = qv.z;
        Qs[(kg + 3) * 64 + r] = qv.w;
    }

    float m_i[4], l_i[4], o[4][8];
#pragma unroll
    for (int i = 0; i < 4; i++) {
        m_i[i] = -1e30f;
        l_i[i] = 0.0f;
#pragma unroll
        for (int j = 0; j < 8; j++) o[i][j] = 0.0f;
    }

    const float scale = 0.08838834764831845f;
    const int ntiles = (q0 >> 6) + 1;

    for (int jt = 0; jt < ntiles; jt++) {
        const int k0 = jt * 64;
        __syncthreads();

        for (int i = tid; i < 2048; i += 256) {
            const int r = i & 63;
            const int kg = (i >> 6) << 2;
            float4 kv = *(const float4*)(Kg + (size_t)(k0 + r) * DHD + kg);
            Ks[(kg + 0) * 64 + r] = kv.x;
            Ks[(kg + 1) * 64 + r] = kv.y;
            Ks[(kg + 2) * 64 + r] = kv.z;
            Ks[(kg + 3) * 64 + r] = kv.w;
        }
        for (int i = tid; i < 2048; i += 256) {
            const int r = i >> 5;
            const int kg = (i & 31) << 2;
            *(float4*)&Vs[r * 128 + kg] =
                *(const float4*)(Vg + (size_t)(k0 + r) * DHD + kg);
        }
        __syncthreads();

        float s[4][4];
#pragma unroll
        for (int i = 0; i < 4; i++)
#pragma unroll
            for (int j = 0; j < 4; j++) s[i][j] = 0.0f;

        for (int k = 0; k < 128; k++) {
            float4 aq = *(const float4*)&Qs[k * 64 + ty * 4];
            float4 bk = *(const float4*)&Ks[k * 64 + tx * 4];
            const float a[4] = {aq.x, aq.y, aq.z, aq.w};
            const float bb2[4] = {bk.x, bk.y, bk.z, bk.w};
#pragma unroll
            for (int i = 0; i < 4; i++)
#pragma unroll
                for (int j = 0; j < 4; j++) s[i][j] += a[i] * bb2[j];
        }

#pragma unroll
        for (int i = 0; i < 4; i++) {
            const int qr = q0 + ty * 4 + i;
#pragma unroll
            for (int j = 0; j < 4; j++) {
                const int kc = k0 + tx * 4 + j;
                s[i][j] = (kc <= qr) ? s[i][j] * scale : -1e30f;
            }
        }

#pragma unroll
        for (int i = 0; i < 4; i++) {
            float rm = fmaxf(fmaxf(s[i][0], s[i][1]), fmaxf(s[i][2], s[i][3]));
#pragma unroll
            for (int off = 8; off > 0; off >>= 1)
                rm = fmaxf(rm, __shfl_xor_sync(0xffffffffu, rm, off));
            const float mn = fmaxf(m_i[i], rm);
            const float alpha = __expf(m_i[i] - mn);
            float rs = 0.0f;
#pragma unroll
            for (int j = 0; j < 4; j++) {
                const float pv = __expf(s[i][j] - mn);
                s[i][j] = pv;
                rs += pv;
            }
#pragma unroll
            for (int off = 8; off > 0; off >>= 1)
                rs += __shfl_xor_sync(0xffffffffu, rs, off);
            l_i[i] = l_i[i] * alpha + rs;
            m_i[i] = mn;
#pragma unroll
            for (int j = 0; j < 8; j++) o[i][j] *= alpha;
#pragma unroll
            for (int j = 0; j < 4; j++)
                Ps[(ty * 4 + i) * 65 + tx * 4 + j] = s[i][j];
        }
        __syncthreads();

        for (int c = 0; c < 64; c++) {
            float pr[4];
#pragma unroll
            for (int i = 0; i < 4; i++) pr[i] = Ps[(ty * 4 + i) * 65 + c];
            float4 v0 = *(const float4*)&Vs[c * 128 + tx * 8];
            float4 v1 = *(const float4*)&Vs[c * 128 + tx * 8 + 4];
            const float vv[8] = {v0.x, v0.y, v0.z, v0.w, v1.x, v1.y, v1.z, v1.w};
#pragma unroll
            for (int i = 0; i < 4; i++)
#pragma unroll
                for (int j = 0; j < 8; j++) o[i][j] += pr[i] * vv[j];
        }
    }

#pragma unroll
    for (int i = 0; i < 4; i++) {
        const int r = q0 + ty * 4 + i;
        const float inv = 1.0f / l_i[i];
        float* dst = g_ctx + ((size_t)b * NT + r) * (NH * DHD) + hq * DHD + tx * 8;
#pragma unroll
        for (int j = 0; j < 8; j++) dst[j] = o[i][j] * inv;
    }
}

// ---------------------------------------------------------------------------
extern "C" void kernel_launch(void* const* d_in, const int* in_sizes, int n_in,
                              void* d_out, int out_size)
{
    const float* x   = (const float*)d_in[0];
    const float* wq  = (const float*)d_in[1];
    const float* wk  = (const float*)d_in[2];
    const float* wv  = (const float*)d_in[3];
    const float* wo  = (const float*)d_in[4];
    const float* qnw = (const float*)d_in[5];
    const float* knw = (const float*)d_in[6];
    float* out = (float*)d_out;

    float *qp, *kp, *vp, *cp;
    __nv_bfloat16 *xh, *xl, *wqh, *wql, *wkh, *wkl, *wvh, *wvl, *woh, *wol, *ch, *cl;
    cudaGetSymbolAddress((void**)&qp, g_q);
    cudaGetSymbolAddress((void**)&kp, g_k);
    cudaGetSymbolAddress((void**)&vp, g_v);
    cudaGetSymbolAddress((void**)&cp, g_ctx);
    cudaGetSymbolAddress((void**)&xh, g_xh);
    cudaGetSymbolAddress((void**)&xl, g_xl);
    cudaGetSymbolAddress((void**)&wqh, g_wqh);
    cudaGetSymbolAddress((void**)&wql, g_wql);
    cudaGetSymbolAddress((void**)&wkh, g_wkh);
    cudaGetSymbolAddress((void**)&wkl, g_wkl);
    cudaGetSymbolAddress((void**)&wvh, g_wvh);
    cudaGetSymbolAddress((void**)&wvl, g_wvl);
    cudaGetSymbolAddress((void**)&woh, g_woh);
    cudaGetSymbolAddress((void**)&wol, g_wol);
    cudaGetSymbolAddress((void**)&ch, g_ch);
    cudaGetSymbolAddress((void**)&cl, g_cl);

    cudaFuncSetAttribute(attn_kernel,
                         cudaFuncAttributeMaxDynamicSharedMemorySize, ATTN_SMEM);
    cudaFuncSetAttribute(gemm_hmma<true>,
                         cudaFuncAttributeMaxDynamicSharedMemorySize, GSMEM);
    cudaFuncSetAttribute(gemm_hmma<false>,
                         cudaFuncAttributeMaxDynamicSharedMemorySize, GSMEM);

    const int M = NB * NT;  // 4096

    // hi/lo splits
    split_kernel<<<(M * ND / 4 + 255) / 256, 256>>>(x, xh, xl, M * ND / 4);
    split_kernel<<<(ND * ND / 4 + 255) / 256, 256>>>(wq, wqh, wql, ND * ND / 4);
    split_kernel<<<(1024 * ND / 4 + 255) / 256, 256>>>(wk, wkh, wkl, 1024 * ND / 4);
    split_kernel<<<(1024 * ND / 4 + 255) / 256, 256>>>(wv, wvh, wvl, 1024 * ND / 4);
    split_kernel<<<(ND * ND / 4 + 255) / 256, 256>>>(wo, woh, wol, ND * ND / 4);
    rope_table_kernel<<<NT, 64>>>();

    // projections (HMMA)
    gemm_hmma<true><<<dim3(NH * DHD / 128, M / 128), 256, GSMEM>>>(
        xh, xl, wqh, wql, qp, NH * DHD, NH);
    gemm_hmma<true><<<dim3(NKV * DHD / 128, M / 128), 256, GSMEM>>>(
        xh, xl, wkh, wkl, kp, NKV * DHD, NKV);
    gemm_hmma<true><<<dim3(NKV * DHD / 128, M / 128), 256, GSMEM>>>(
        xh, xl, wvh, wvl, vp, NKV * DHD, NKV);

    normrope_kernel<<<NB * NH * NT / 8, 256>>>(qp, qnw);
    normrope_kernel<<<NB * NKV * NT / 8, 256>>>(kp, knw);

    attn_kernel<<<dim3(NT / 64, NB * NH), 256, ATTN_SMEM>>>();

    // output projection
    split_kernel<<<(M * ND / 4 + 255) / 256, 256>>>(cp, ch, cl, M * ND / 4);
    gemm_hmma<false><<<dim3(ND / 128, M / 128), 256, GSMEM>>>(
        ch, cl, woh, wol, out, ND, ND);
}

// round 5
// speedup vs baseline: 3.2873x; 1.7832x over previous
#include <cuda_runtime.h>
#include <cuda_bf16.h>
#include <math.h>
#include <stdint.h>

#define NB  2
#define NT  2048
#define ND  2048
#define NH  16
#define NKV 8
#define DHD 128

// ---------------- device scratch (no allocations allowed) ----------------
__device__ float g_q[(size_t)NB * NH * NT * DHD];
__device__ float g_k[(size_t)NB * NKV * NT * DHD];
__device__ float g_v[(size_t)NB * NKV * NT * DHD];
__device__ float g_cos[NT * 64];
__device__ float g_sin[NT * 64];

__device__ __nv_bfloat16 g_xh[(size_t)NB * NT * ND];
__device__ __nv_bfloat16 g_xl[(size_t)NB * NT * ND];
__device__ __nv_bfloat16 g_wqh[(size_t)NH * DHD * ND];
__device__ __nv_bfloat16 g_wql[(size_t)NH * DHD * ND];
__device__ __nv_bfloat16 g_wkh[(size_t)NKV * DHD * ND];
__device__ __nv_bfloat16 g_wkl[(size_t)NKV * DHD * ND];
__device__ __nv_bfloat16 g_wvh[(size_t)NKV * DHD * ND];
__device__ __nv_bfloat16 g_wvl[(size_t)NKV * DHD * ND];
__device__ __nv_bfloat16 g_woh[(size_t)ND * NH * DHD];
__device__ __nv_bfloat16 g_wol[(size_t)ND * NH * DHD];
__device__ __nv_bfloat16 g_ch[(size_t)NB * NT * NH * DHD];
__device__ __nv_bfloat16 g_cl[(size_t)NB * NT * NH * DHD];

// attention operands, bf16 hi/lo, head-major [b,h,t,128]
__device__ __nv_bfloat16 g_qh[(size_t)NB * NH * NT * DHD];
__device__ __nv_bfloat16 g_ql[(size_t)NB * NH * NT * DHD];
__device__ __nv_bfloat16 g_kbh[(size_t)NB * NKV * NT * DHD];
__device__ __nv_bfloat16 g_kbl[(size_t)NB * NKV * NT * DHD];
__device__ __nv_bfloat16 g_vbh[(size_t)NB * NKV * NT * DHD];
__device__ __nv_bfloat16 g_vbl[(size_t)NB * NKV * NT * DHD];

// ---------------- PTX helpers (base-target ISA only) ----------------
__device__ __forceinline__ uint32_t smem_u32(const void* p) {
    uint32_t a;
    asm("{ .reg .u64 t; cvta.to.shared.u64 t, %1; cvt.u32.u64 %0, t; }"
        : "=r"(a) : "l"(p));
    return a;
}
__device__ __forceinline__ void ldm_x4(uint32_t* r, uint32_t addr) {
    asm volatile("ldmatrix.sync.aligned.m8n8.x4.shared.b16 {%0,%1,%2,%3}, [%4];"
                 : "=r"(r[0]), "=r"(r[1]), "=r"(r[2]), "=r"(r[3]) : "r"(addr));
}
__device__ __forceinline__ void ldm_x4_t(uint32_t* r, uint32_t addr) {
    asm volatile("ldmatrix.sync.aligned.m8n8.x4.trans.shared.b16 {%0,%1,%2,%3}, [%4];"
                 : "=r"(r[0]), "=r"(r[1]), "=r"(r[2]), "=r"(r[3]) : "r"(addr));
}
__device__ __forceinline__ void mma16816(float* c, const uint32_t* a, const uint32_t* b) {
    asm volatile(
        "mma.sync.aligned.m16n8k16.row.col.f32.bf16.bf16.f32 "
        "{%0,%1,%2,%3}, {%4,%5,%6,%7}, {%8,%9}, {%0,%1,%2,%3};"
        : "+f"(c[0]), "+f"(c[1]), "+f"(c[2]), "+f"(c[3])
        : "r"(a[0]), "r"(a[1]), "r"(a[2]), "r"(a[3]), "r"(b[0]), "r"(b[1]));
}
__device__ __forceinline__ void cpa16(uint32_t dst, const void* src) {
    asm volatile("cp.async.cg.shared.global [%0], [%1], 16;" :: "r"(dst), "l"(src));
}
__device__ __forceinline__ void cpa_commit() {
    asm volatile("cp.async.commit_group;" ::: "memory");
}
template <int N> __device__ __forceinline__ void cpa_wait() {
    asm volatile("cp.async.wait_group %0;" :: "n"(N) : "memory");
}
__device__ __forceinline__ float ex2f(float x) {
    float r;
    asm("ex2.approx.f32 %0, %1;" : "=f"(r) : "f"(x));
    return r;
}
__device__ __forceinline__ uint32_t packbf(float lo, float hi) {
    uint32_t r;
    asm("cvt.rn.bf16x2.f32 %0, %1, %2;" : "=r"(r) : "f"(hi), "f"(lo));
    return r;
}
__device__ __forceinline__ float bflo(uint32_t u) { return __uint_as_float(u << 16); }
__device__ __forceinline__ float bfhi(uint32_t u) { return __uint_as_float(u & 0xffff0000u); }

// ---------------- fp32 -> bf16 hi/lo split ----------------
__global__ void __launch_bounds__(256) split_kernel(
    const float* __restrict__ s, __nv_bfloat16* __restrict__ h,
    __nv_bfloat16* __restrict__ l, int n4)
{
    int i = blockIdx.x * 256 + threadIdx.x;
    if (i >= n4) return;
    float4 v = ((const float4*)s)[i];
    uint32_t h0 = packbf(v.x, v.y);
    uint32_t h1 = packbf(v.z, v.w);
    uint32_t l0 = packbf(v.x - bflo(h0), v.y - bfhi(h0));
    uint32_t l1 = packbf(v.z - bflo(h1), v.w - bfhi(h1));
    uint2 hp = {h0, h1}, lp = {l0, l1};
    ((uint2*)h)[i] = hp;
    ((uint2*)l)[i] = lp;
}

// ---------------- HMMA bf16-split GEMM: C = A @ W^T ----------------
#define GK       2048
#define ROWB     80
#define TILEB    10240
#define STAGEB   40960
#define GSMEM    (2 * STAGEB)

__device__ __forceinline__ void load_chunk(
    uint32_t base, const __nv_bfloat16* const* srcs, int tid, int c)
{
#pragma unroll
    for (int t = 0; t < 4; t++) {
#pragma unroll
        for (int p = 0; p < 2; p++) {
            const int idx = tid + p * 256;
            const int row = idx >> 2;
            const int seg = idx & 3;
            cpa16(base + t * TILEB + row * ROWB + seg * 16,
                  srcs[t] + (size_t)row * GK + c * 32 + seg * 8);
        }
    }
    cpa_commit();
}

__device__ __forceinline__ void compute_chunk(
    uint32_t base, int wm, int wn, uint32_t a_off, uint32_t b_off,
    float acc[4][4][4])
{
#pragma unroll
    for (int kk = 0; kk < 2; kk++) {
        const uint32_t koff = kk * 32;
        const uint32_t paH = base + wm * 64 * ROWB + koff + a_off;
        const uint32_t pbH = base + 2 * TILEB + wn * 32 * ROWB + koff + b_off;

        uint32_t af[4][4], bf0[2][4], bf1[2][4];
#pragma unroll
        for (int i = 0; i < 4; i++) ldm_x4(af[i], paH + i * (16 * ROWB));
        ldm_x4(bf0[0], pbH);
        ldm_x4(bf0[1], pbH + 16 * ROWB);
        ldm_x4(bf1[0], pbH + TILEB);
        ldm_x4(bf1[1], pbH + TILEB + 16 * ROWB);

#pragma unroll
        for (int i = 0; i < 4; i++)
#pragma unroll
            for (int j = 0; j < 4; j++)
                mma16816(acc[i][j], af[i], &bf0[j >> 1][(j & 1) * 2]);
#pragma unroll
        for (int i = 0; i < 4; i++)
#pragma unroll
            for (int j = 0; j < 4; j++)
                mma16816(acc[i][j], af[i], &bf1[j >> 1][(j & 1) * 2]);
#pragma unroll
        for (int i = 0; i < 4; i++) ldm_x4(af[i], paH + TILEB + i * (16 * ROWB));
#pragma unroll
        for (int i = 0; i < 4; i++)
#pragma unroll
            for (int j = 0; j < 4; j++)
                mma16816(acc[i][j], af[i], &bf0[j >> 1][(j & 1) * 2]);
    }
}

template <bool HEAD_MAJOR>
__global__ void __launch_bounds__(256) gemm_hmma(
    const __nv_bfloat16* __restrict__ Ah, const __nv_bfloat16* __restrict__ Al,
    const __nv_bfloat16* __restrict__ Bh, const __nv_bfloat16* __restrict__ Bl,
    float* __restrict__ C, int N, int heads)
{
    extern __shared__ char smem[];
    const uint32_t sb = smem_u32(smem);
    const int tid = threadIdx.x;
    const int lane = tid & 31;
    const int w = tid >> 5;
    const int wm = w >> 2;
    const int wn = w & 3;
    const int m0 = blockIdx.y * 128;
    const int n0 = blockIdx.x * 128;

    const __nv_bfloat16* srcs[4] = {
        Ah + (size_t)m0 * GK, Al + (size_t)m0 * GK,
        Bh + (size_t)n0 * GK, Bl + (size_t)n0 * GK};

    const uint32_t a_off = (uint32_t)(lane & 15) * ROWB + (uint32_t)(lane >> 4) * 16;
    const uint32_t b_off = (uint32_t)((lane & 7) + ((lane >> 4) << 3)) * ROWB +
                           (uint32_t)((lane >> 3) & 1) * 16;

    float acc[4][4][4];
#pragma unroll
    for (int i = 0; i < 4; i++)
#pragma unroll
        for (int j = 0; j < 4; j++)
#pragma unroll
            for (int r = 0; r < 4; r++) acc[i][j][r] = 0.0f;

    load_chunk(sb, srcs, tid, 0);

    const int nchunks = GK / 32;
    for (int c = 0; c < nchunks; c++) {
        cpa_wait<0>();
        __syncthreads();
        if (c + 1 < nchunks)
            load_chunk(sb + ((c + 1) & 1) * STAGEB, srcs, tid, c + 1);
        compute_chunk(sb + (c & 1) * STAGEB, wm, wn, a_off, b_off, acc);
    }

    const int g = lane >> 2;
    const int tg = lane & 3;
#pragma unroll
    for (int i = 0; i < 4; i++) {
        const int mrow0 = m0 + wm * 64 + i * 16 + g;
#pragma unroll
        for (int j = 0; j < 4; j++) {
            const int col = wn * 32 + j * 8 + tg * 2;
#pragma unroll
            for (int h2 = 0; h2 < 2; h2++) {
                const int m = mrow0 + h2 * 8;
                const int b = m >> 11;
                const int t = m & (NT - 1);
                float2 v = {acc[i][j][h2 * 2], acc[i][j][h2 * 2 + 1]};
                if (HEAD_MAJOR) {
                    const int head = blockIdx.x;
                    *(float2*)(C + (((size_t)b * heads + head) * NT + t) * DHD + col) = v;
                } else {
                    *(float2*)(C + (size_t)m * N + n0 + col) = v;
                }
            }
        }
    }
}

// ---------------- RoPE table ----------------
__global__ void rope_table_kernel() {
    const int t = blockIdx.x;
    const int fi = threadIdx.x;
    const float invf = (float)exp(-(double)fi * (13.815510557964274 / 64.0));
    const float arg = (float)t * invf;
    float s, c;
    sincosf(arg, &s, &c);
    g_cos[t * 64 + fi] = c;
    g_sin[t * 64 + fi] = s;
}

// ---------------- fused RMSNorm + RoPE + bf16 hi/lo split ----------------
__global__ void __launch_bounds__(256) normrope_kernel(
    const float* __restrict__ buf, __nv_bfloat16* __restrict__ oh,
    __nv_bfloat16* __restrict__ ol, const float* __restrict__ w)
{
    const int row = blockIdx.x * 8 + (threadIdx.x >> 5);
    const int lid = threadIdx.x & 31;
    const int t = row & (NT - 1);
    const float* p = buf + (size_t)row * DHD + lid * 4;

    float4 v = *(const float4*)p;
    float ss = v.x * v.x + v.y * v.y + v.z * v.z + v.w * v.w;
#pragma unroll
    for (int o = 16; o > 0; o >>= 1) ss += __shfl_xor_sync(0xffffffffu, ss, o);
    const float rn = rsqrtf(ss * (1.0f / 128.0f) + 1e-6f);

    float4 wv = *(const float4*)(w + lid * 4);
    float x0 = v.x * rn * wv.x, x1 = v.y * rn * wv.y;
    float x2 = v.z * rn * wv.z, x3 = v.w * rn * wv.w;

    const float p0 = __shfl_xor_sync(0xffffffffu, x0, 16);
    const float p1 = __shfl_xor_sync(0xffffffffu, x1, 16);
    const float p2 = __shfl_xor_sync(0xffffffffu, x2, 16);
    const float p3 = __shfl_xor_sync(0xffffffffu, x3, 16);

    const int fi0 = (lid & 15) * 4;
    float4 cv = *(const float4*)(g_cos + t * 64 + fi0);
    float4 sv = *(const float4*)(g_sin + t * 64 + fi0);
    const float sg = (lid < 16) ? -1.0f : 1.0f;

    float o0 = x0 * cv.x + sg * p0 * sv.x;
    float o1 = x1 * cv.y + sg * p1 * sv.y;
    float o2 = x2 * cv.z + sg * p2 * sv.z;
    float o3 = x3 * cv.w + sg * p3 * sv.w;

    uint32_t h0 = packbf(o0, o1), h1 = packbf(o2, o3);
    uint32_t l0 = packbf(o0 - bflo(h0), o1 - bfhi(h0));
    uint32_t l1 = packbf(o2 - bflo(h1), o3 - bfhi(h1));
    uint2 hv = {h0, h1}, lv = {l0, l1};
    ((uint2*)(oh + (size_t)row * DHD))[lid] = hv;
    ((uint2*)(ol + (size_t)row * DHD))[lid] = lv;
}

// ---------------- HMMA flash attention, causal, GQA ----------------
// BQ=128, BK=64, 8 warps x 16 rows. hi/lo 3-product for QK^T and PV.
#define AROW   272                 // smem row stride bytes (128 dh bf16 + pad)
#define QTB    (128 * AROW)        // 34816
#define KTB    (64 * AROW)         // 17408
#define KVSTG  (4 * KTB)           // Kh,Kl,Vh,Vl = 69632
#define ASMEM  (2 * QTB + 2 * KVSTG)   // 208896

__global__ void __launch_bounds__(256) attn_mma_kernel()
{
    extern __shared__ char smem[];
    const uint32_t sb = smem_u32(smem);
    const int tid = threadIdx.x;
    const int lane = tid & 31;
    const int w = tid >> 5;
    const int bh = blockIdx.y;
    const int b = bh >> 4;
    const int hq = bh & 15;
    const int hk = hq >> 1;
    const int qt = (NT / 128 - 1) - blockIdx.x;  // biggest tiles first
    const int q0 = qt * 128;
    const int last = 2 * qt + 1;

    const __nv_bfloat16* Qhg = g_qh + (((size_t)b * NH + hq) * NT + q0) * DHD;
    const __nv_bfloat16* Qlg = g_ql + (((size_t)b * NH + hq) * NT + q0) * DHD;
    const __nv_bfloat16* Khg = g_kbh + ((size_t)b * NKV + hk) * NT * DHD;
    const __nv_bfloat16* Klg = g_kbl + ((size_t)b * NKV + hk) * NT * DHD;
    const __nv_bfloat16* Vhg = g_vbh + ((size_t)b * NKV + hk) * NT * DHD;
    const __nv_bfloat16* Vlg = g_vbl + ((size_t)b * NKV + hk) * NT * DHD;

    const uint32_t sQh = sb, sQl = sb + QTB;
    const uint32_t sKV0 = sb + 2 * QTB;

    // ---- prologue: Q tiles + KV stage 0 ----
#pragma unroll
    for (int i = 0; i < 8; i++) {
        const int idx = tid + i * 256;
        const int r = idx >> 4, ch = idx & 15;
        cpa16(sQh + r * AROW + ch * 16, Qhg + (size_t)r * DHD + ch * 8);
        cpa16(sQl + r * AROW + ch * 16, Qlg + (size_t)r * DHD + ch * 8);
    }
    cpa_commit();

    auto load_kv = [&](int stage, int jt) {
        const uint32_t base = sKV0 + stage * KVSTG;
        const size_t off = (size_t)jt * 64 * DHD;
        const __nv_bfloat16* srcs[4] = {Khg + off, Klg + off, Vhg + off, Vlg + off};
#pragma unroll
        for (int t = 0; t < 4; t++)
#pragma unroll
            for (int i = 0; i < 4; i++) {
                const int idx = tid + i * 256;
                const int r = idx >> 4, ch = idx & 15;
                cpa16(base + t * KTB + r * AROW + ch * 16,
                      srcs[t] + (size_t)r * DHD + ch * 8);
            }
        cpa_commit();
    };
    load_kv(0, 0);

    cpa_wait<1>();
    __syncthreads();

    const uint32_t a_off = (uint32_t)(lane & 15) * AROW + (uint32_t)(lane >> 4) * 16;
    const uint32_t kb_off = (uint32_t)((lane & 7) + ((lane >> 4) << 3)) * AROW +
                            (uint32_t)((lane >> 3) & 1) * 16;
    const uint32_t vb_off = (uint32_t)((lane & 7) + (((lane >> 3) & 1) << 3)) * AROW +
                            (uint32_t)(lane >> 4) * 16;

    uint32_t qh[8][4];
#pragma unroll
    for (int c = 0; c < 8; c++) ldm_x4(qh[c], sQh + w * 16 * AROW + a_off + c * 32);

    float oacc[16][4];
#pragma unroll
    for (int n = 0; n < 16; n++)
#pragma unroll
        for (int r = 0; r < 4; r++) oacc[n][r] = 0.0f;
    float m0 = -1e30f, m1 = -1e30f, l0 = 0.0f, l1 = 0.0f;

    const float CEXP = 0.12751740493262602f;  // (1/sqrt(128)) * log2(e)
    const int r0g = q0 + w * 16 + (lane >> 2);
    const int r1g = r0g + 8;

    for (int jt = 0; jt <= last; jt++) {
        __syncthreads();
        if (jt < last) {
            load_kv((jt + 1) & 1, jt + 1);
            cpa_wait<1>();
        } else {
            cpa_wait<0>();
        }
        __syncthreads();

        const uint32_t kb = sKV0 + (jt & 1) * KVSTG;

        // ---- S = Q K^T (3 products) ----
        float s[8][4];
#pragma unroll
        for (int j = 0; j < 8; j++)
#pragma unroll
            for (int r = 0; r < 4; r++) s[j][r] = 0.0f;

#pragma unroll
        for (int c = 0; c < 8; c++) {
            uint32_t kh[4][4], kl[4][4], ql[4];
#pragma unroll
            for (int m = 0; m < 4; m++)
                ldm_x4(kh[m], kb + kb_off + m * (16 * AROW) + c * 32);
#pragma unroll
            for (int m = 0; m < 4; m++)
                ldm_x4(kl[m], kb + KTB + kb_off + m * (16 * AROW) + c * 32);
            ldm_x4(ql, sQl + w * 16 * AROW + a_off + c * 32);
#pragma unroll
            for (int j = 0; j < 8; j++) {
                mma16816(s[j], qh[c], &kh[j >> 1][(j & 1) * 2]);
                mma16816(s[j], qh[c], &kl[j >> 1][(j & 1) * 2]);
                mma16816(s[j], ql, &kh[j >> 1][(j & 1) * 2]);
            }
        }

        // ---- mask + online softmax ----
        const int k0 = jt * 64;
        if (k0 + 63 > q0 + w * 16) {
#pragma unroll
            for (int j = 0; j < 8; j++) {
                const int col0 = k0 + j * 8 + (lane & 3) * 2;
                if (col0 > r0g) s[j][0] = -1e30f;
                if (col0 + 1 > r0g) s[j][1] = -1e30f;
                if (col0 > r1g) s[j][2] = -1e30f;
                if (col0 + 1 > r1g) s[j][3] = -1e30f;
            }
        }
        float rmax0 = -1e30f, rmax1 = -1e30f;
#pragma unroll
        for (int j = 0; j < 8; j++) {
            rmax0 = fmaxf(rmax0, fmaxf(s[j][0], s[j][1]));
            rmax1 = fmaxf(rmax1, fmaxf(s[j][2], s[j][3]));
        }
        rmax0 = fmaxf(rmax0, __shfl_xor_sync(0xffffffffu, rmax0, 1));
        rmax0 = fmaxf(rmax0, __shfl_xor_sync(0xffffffffu, rmax0, 2));
        rmax1 = fmaxf(rmax1, __shfl_xor_sync(0xffffffffu, rmax1, 1));
        rmax1 = fmaxf(rmax1, __shfl_xor_sync(0xffffffffu, rmax1, 2));

        const float mn0 = fmaxf(m0, rmax0);
        const float mn1 = fmaxf(m1, rmax1);
        const float al0 = ex2f((m0 - mn0) * CEXP);
        const float al1 = ex2f((m1 - mn1) * CEXP);
        m0 = mn0;
        m1 = mn1;

        float sum0 = 0.0f, sum1 = 0.0f;
#pragma unroll
        for (int j = 0; j < 8; j++) {
            s[j][0] = ex2f((s[j][0] - mn0) * CEXP);
            s[j][1] = ex2f((s[j][1] - mn0) * CEXP);
            s[j][2] = ex2f((s[j][2] - mn1) * CEXP);
            s[j][3] = ex2f((s[j][3] - mn1) * CEXP);
            sum0 += s[j][0] + s[j][1];
            sum1 += s[j][2] + s[j][3];
        }
        sum0 += __shfl_xor_sync(0xffffffffu, sum0, 1);
        sum0 += __shfl_xor_sync(0xffffffffu, sum0, 2);
        sum1 += __shfl_xor_sync(0xffffffffu, sum1, 1);
        sum1 += __shfl_xor_sync(0xffffffffu, sum1, 2);
        l0 = l0 * al0 + sum0;
        l1 = l1 * al1 + sum1;

#pragma unroll
        for (int n = 0; n < 16; n++) {
            oacc[n][0] *= al0;
            oacc[n][1] *= al0;
            oacc[n][2] *= al1;
            oacc[n][3] *= al1;
        }

        // ---- O += P V (3 products, P hi/lo built in registers) ----
        const uint32_t vbh = kb + 2 * KTB;
        const uint32_t vbl = kb + 3 * KTB;
#pragma unroll
        for (int kt = 0; kt < 4; kt++) {
            const int j0 = 2 * kt, j1 = 2 * kt + 1;
            uint32_t ph[4], pl[4];
            ph[0] = packbf(s[j0][0], s[j0][1]);
            ph[1] = packbf(s[j0][2], s[j0][3]);
            ph[2] = packbf(s[j1][0], s[j1][1]);
            ph[3] = packbf(s[j1][2], s[j1][3]);
            pl[0] = packbf(s[j0][0] - bflo(ph[0]), s[j0][1] - bfhi(ph[0]));
            pl[1] = packbf(s[j0][2] - bflo(ph[1]), s[j0][3] - bfhi(ph[1]));
            pl[2] = packbf(s[j1][0] - bflo(ph[2]), s[j1][1] - bfhi(ph[2]));
            pl[3] = packbf(s[j1][2] - bflo(ph[3]), s[j1][3] - bfhi(ph[3]));
#pragma unroll
            for (int d = 0; d < 8; d++) {
                uint32_t vh[4], vl[4];
                ldm_x4_t(vh, vbh + vb_off + kt * (16 * AROW) + d * 32);
                ldm_x4_t(vl, vbl + vb_off + kt * (16 * AROW) + d * 32);
                mma16816(oacc[2 * d], ph, vh);
                mma16816(oacc[2 * d + 1], ph, vh + 2);
                mma16816(oacc[2 * d], pl, vh);
                mma16816(oacc[2 * d + 1], pl, vh + 2);
                mma16816(oacc[2 * d], ph, vl);
                mma16816(oacc[2 * d + 1], ph, vl + 2);
            }
        }
    }

    // ---- epilogue: divide by l, write bf16 hi/lo ctx ----
    const float inv0 = 1.0f / l0;
    const float inv1 = 1.0f / l1;
    __nv_bfloat16* chp = g_ch;
    __nv_bfloat16* clp = g_cl;
    const size_t rowA = ((size_t)b * NT + r0g) * (NH * DHD) + hq * DHD;
    const size_t rowB = ((size_t)b * NT + r1g) * (NH * DHD) + hq * DHD;
#pragma unroll
    for (int n = 0; n < 16; n++) {
        const int col = n * 8 + (lane & 3) * 2;
        float v0 = oacc[n][0] * inv0, v1 = oacc[n][1] * inv0;
        uint32_t h = packbf(v0, v1);
        uint32_t lo = packbf(v0 - bflo(h), v1 - bfhi(h));
        *(uint32_t*)(chp + rowA + col) = h;
        *(uint32_t*)(clp + rowA + col) = lo;
        float v2 = oacc[n][2] * inv1, v3 = oacc[n][3] * inv1;
        uint32_t h2 = packbf(v2, v3);
        uint32_t lo2 = packbf(v2 - bflo(h2), v3 - bfhi(h2));
        *(uint32_t*)(chp + rowB + col) = h2;
        *(uint32_t*)(clp + rowB + col) = lo2;
    }
}

// ---------------------------------------------------------------------------
extern "C" void kernel_launch(void* const* d_in, const int* in_sizes, int n_in,
                              void* d_out, int out_size)
{
    const float* x   = (const float*)d_in[0];
    const float* wq  = (const float*)d_in[1];
    const float* wk  = (const float*)d_in[2];
    const float* wv  = (const float*)d_in[3];
    const float* wo  = (const float*)d_in[4];
    const float* qnw = (const float*)d_in[5];
    const float* knw = (const float*)d_in[6];
    float* out = (float*)d_out;

    float *qp, *kp, *vp;
    __nv_bfloat16 *xh, *xl, *wqh, *wql, *wkh, *wkl, *wvh, *wvl, *woh, *wol, *ch, *cl;
    __nv_bfloat16 *qhp, *qlp, *kbh, *kbl, *vbh, *vbl;
    cudaGetSymbolAddress((void**)&qp, g_q);
    cudaGetSymbolAddress((void**)&kp, g_k);
    cudaGetSymbolAddress((void**)&vp, g_v);
    cudaGetSymbolAddress((void**)&xh, g_xh);
    cudaGetSymbolAddress((void**)&xl, g_xl);
    cudaGetSymbolAddress((void**)&wqh, g_wqh);
    cudaGetSymbolAddress((void**)&wql, g_wql);
    cudaGetSymbolAddress((void**)&wkh, g_wkh);
    cudaGetSymbolAddress((void**)&wkl, g_wkl);
    cudaGetSymbolAddress((void**)&wvh, g_wvh);
    cudaGetSymbolAddress((void**)&wvl, g_wvl);
    cudaGetSymbolAddress((void**)&woh, g_woh);
    cudaGetSymbolAddress((void**)&wol, g_wol);
    cudaGetSymbolAddress((void**)&ch, g_ch);
    cudaGetSymbolAddress((void**)&cl, g_cl);
    cudaGetSymbolAddress((void**)&qhp, g_qh);
    cudaGetSymbolAddress((void**)&qlp, g_ql);
    cudaGetSymbolAddress((void**)&kbh, g_kbh);
    cudaGetSymbolAddress((void**)&kbl, g_kbl);
    cudaGetSymbolAddress((void**)&vbh, g_vbh);
    cudaGetSymbolAddress((void**)&vbl, g_vbl);

    cudaFuncSetAttribute(gemm_hmma<true>,
                         cudaFuncAttributeMaxDynamicSharedMemorySize, GSMEM);
    cudaFuncSetAttribute(gemm_hmma<false>,
                         cudaFuncAttributeMaxDynamicSharedMemorySize, GSMEM);
    cudaFuncSetAttribute(attn_mma_kernel,
                         cudaFuncAttributeMaxDynamicSharedMemorySize, ASMEM);

    const int M = NB * NT;  // 4096

    // hi/lo splits + rope table
    split_kernel<<<(M * ND / 4 + 255) / 256, 256>>>(x, xh, xl, M * ND / 4);
    split_kernel<<<(ND * ND / 4 + 255) / 256, 256>>>(wq, wqh, wql, ND * ND / 4);
    split_kernel<<<(1024 * ND / 4 + 255) / 256, 256>>>(wk, wkh, wkl, 1024 * ND / 4);
    split_kernel<<<(1024 * ND / 4 + 255) / 256, 256>>>(wv, wvh, wvl, 1024 * ND / 4);
    split_kernel<<<(ND * ND / 4 + 255) / 256, 256>>>(wo, woh, wol, ND * ND / 4);
    rope_table_kernel<<<NT, 64>>>();

    // projections (HMMA, fp32 out)
    gemm_hmma<true><<<dim3(NH * DHD / 128, M / 128), 256, GSMEM>>>(
        xh, xl, wqh, wql, qp, NH * DHD, NH);
    gemm_hmma<true><<<dim3(NKV * DHD / 128, M / 128), 256, GSMEM>>>(
        xh, xl, wkh, wkl, kp, NKV * DHD, NKV);
    gemm_hmma<true><<<dim3(NKV * DHD / 128, M / 128), 256, GSMEM>>>(
        xh, xl, wvh, wvl, vp, NKV * DHD, NKV);

    // norm+rope -> bf16 hi/lo; V -> bf16 hi/lo
    normrope_kernel<<<NB * NH * NT / 8, 256>>>(qp, qhp, qlp, qnw);
    normrope_kernel<<<NB * NKV * NT / 8, 256>>>(kp, kbh, kbl, knw);
    split_kernel<<<((int)((size_t)NB * NKV * NT * DHD / 4) + 255) / 256, 256>>>(
        vp, vbh, vbl, (int)((size_t)NB * NKV * NT * DHD / 4));

    // HMMA flash attention -> ch/cl (bf16 hi/lo ctx)
    attn_mma_kernel<<<dim3(NT / 128, NB * NH), 256, ASMEM>>>();

    // output projection
    gemm_hmma<false><<<dim3(ND / 128, M / 128), 256, GSMEM>>>(
        ch, cl, woh, wol, out, ND, ND);
}

// round 7
// speedup vs baseline: 3.9004x; 1.1865x over previous
#include <cuda_runtime.h>
#include <cuda_bf16.h>
#include <math.h>
#include <stdint.h>

#define NB  2
#define NT  2048
#define ND  2048
#define NH  16
#define NKV 8
#define DHD 128

// ---------------- device scratch (no allocations allowed) ----------------
__device__ float g_q[(size_t)NB * NH * NT * DHD];
__device__ float g_k[(size_t)NB * NKV * NT * DHD];
__device__ float g_cos[NT * 64];
__device__ float g_sin[NT * 64];

__device__ __nv_bfloat16 g_xh[(size_t)NB * NT * ND];
__device__ __nv_bfloat16 g_xl[(size_t)NB * NT * ND];
__device__ __nv_bfloat16 g_wqh[(size_t)NH * DHD * ND];
__device__ __nv_bfloat16 g_wql[(size_t)NH * DHD * ND];
__device__ __nv_bfloat16 g_wkh[(size_t)NKV * DHD * ND];
__device__ __nv_bfloat16 g_wkl[(size_t)NKV * DHD * ND];
__device__ __nv_bfloat16 g_wvh[(size_t)NKV * DHD * ND];
__device__ __nv_bfloat16 g_wvl[(size_t)NKV * DHD * ND];
__device__ __nv_bfloat16 g_woh[(size_t)ND * NH * DHD];
__device__ __nv_bfloat16 g_wol[(size_t)ND * NH * DHD];
__device__ __nv_bfloat16 g_ch[(size_t)NB * NT * NH * DHD];
__device__ __nv_bfloat16 g_cl[(size_t)NB * NT * NH * DHD];

// attention operands, bf16 hi/lo, head-major [b,h,t,128]
__device__ __nv_bfloat16 g_qh[(size_t)NB * NH * NT * DHD];
__device__ __nv_bfloat16 g_ql[(size_t)NB * NH * NT * DHD];
__device__ __nv_bfloat16 g_kbh[(size_t)NB * NKV * NT * DHD];
__device__ __nv_bfloat16 g_kbl[(size_t)NB * NKV * NT * DHD];
__device__ __nv_bfloat16 g_vbh[(size_t)NB * NKV * NT * DHD];
__device__ __nv_bfloat16 g_vbl[(size_t)NB * NKV * NT * DHD];

// ---------------- PTX helpers (base-target ISA only) ----------------
__device__ __forceinline__ uint32_t smem_u32(const void* p) {
    uint32_t a;
    asm("{ .reg .u64 t; cvta.to.shared.u64 t, %1; cvt.u32.u64 %0, t; }"
        : "=r"(a) : "l"(p));
    return a;
}
__device__ __forceinline__ void ldm_x4(uint32_t* r, uint32_t addr) {
    asm volatile("ldmatrix.sync.aligned.m8n8.x4.shared.b16 {%0,%1,%2,%3}, [%4];"
                 : "=r"(r[0]), "=r"(r[1]), "=r"(r[2]), "=r"(r[3]) : "r"(addr));
}
__device__ __forceinline__ void ldm_x4_t(uint32_t* r, uint32_t addr) {
    asm volatile("ldmatrix.sync.aligned.m8n8.x4.trans.shared.b16 {%0,%1,%2,%3}, [%4];"
                 : "=r"(r[0]), "=r"(r[1]), "=r"(r[2]), "=r"(r[3]) : "r"(addr));
}
__device__ __forceinline__ void mma16816(float* c, const uint32_t* a, const uint32_t* b) {
    asm volatile(
        "mma.sync.aligned.m16n8k16.row.col.f32.bf16.bf16.f32 "
        "{%0,%1,%2,%3}, {%4,%5,%6,%7}, {%8,%9}, {%0,%1,%2,%3};"
        : "+f"(c[0]), "+f"(c[1]), "+f"(c[2]), "+f"(c[3])
        : "r"(a[0]), "r"(a[1]), "r"(a[2]), "r"(a[3]), "r"(b[0]), "r"(b[1]));
}
__device__ __forceinline__ void cpa16(uint32_t dst, const void* src) {
    asm volatile("cp.async.cg.shared.global [%0], [%1], 16;" :: "r"(dst), "l"(src));
}
__device__ __forceinline__ void cpa_commit() {
    asm volatile("cp.async.commit_group;" ::: "memory");
}
template <int N> __device__ __forceinline__ void cpa_wait() {
    asm volatile("cp.async.wait_group %0;" :: "n"(N) : "memory");
}
__device__ __forceinline__ float ex2f(float x) {
    float r;
    asm("ex2.approx.f32 %0, %1;" : "=f"(r) : "f"(x));
    return r;
}
__device__ __forceinline__ uint32_t packbf(float lo, float hi) {
    uint32_t r;
    asm("cvt.rn.bf16x2.f32 %0, %1, %2;" : "=r"(r) : "f"(hi), "f"(lo));
    return r;
}
__device__ __forceinline__ float bflo(uint32_t u) { return __uint_as_float(u << 16); }
__device__ __forceinline__ float bfhi(uint32_t u) { return __uint_as_float(u & 0xffff0000u); }

// ---------------- fp32 -> bf16 hi/lo split ----------------
__global__ void __launch_bounds__(256) split_kernel(
    const float* __restrict__ s, __nv_bfloat16* __restrict__ h,
    __nv_bfloat16* __restrict__ l, int n4)
{
    int i = blockIdx.x * 256 + threadIdx.x;
    if (i >= n4) return;
    float4 v = ((const float4*)s)[i];
    uint32_t h0 = packbf(v.x, v.y);
    uint32_t h1 = packbf(v.z, v.w);
    uint32_t l0 = packbf(v.x - bflo(h0), v.y - bfhi(h0));
    uint32_t l1 = packbf(v.z - bflo(h1), v.w - bfhi(h1));
    uint2 hp = {h0, h1}, lp = {l0, l1};
    ((uint2*)h)[i] = hp;
    ((uint2*)l)[i] = lp;
}

// ---------------- HMMA bf16-split GEMM core ----------------
#define GK       2048
#define ROWB     80
#define TILEB    10240
#define STAGEB   40960
#define GSMEM    (2 * STAGEB)

__device__ __forceinline__ void load_chunk(
    uint32_t base, const __nv_bfloat16* const* srcs, int tid, int c)
{
#pragma unroll
    for (int t = 0; t < 4; t++) {
#pragma unroll
        for (int p = 0; p < 2; p++) {
            const int idx = tid + p * 256;
            const int row = idx >> 2;
            const int seg = idx & 3;
            cpa16(base + t * TILEB + row * ROWB + seg * 16,
                  srcs[t] + (size_t)row * GK + c * 32 + seg * 8);
        }
    }
    cpa_commit();
}

__device__ __forceinline__ void compute_chunk(
    uint32_t base, int wm, int wn, uint32_t a_off, uint32_t b_off,
    float acc[4][4][4])
{
#pragma unroll
    for (int kk = 0; kk < 2; kk++) {
        const uint32_t koff = kk * 32;
        const uint32_t paH = base + wm * 64 * ROWB + koff + a_off;
        const uint32_t pbH = base + 2 * TILEB + wn * 32 * ROWB + koff + b_off;

        uint32_t af[4][4], bf0[2][4], bf1[2][4];
#pragma unroll
        for (int i = 0; i < 4; i++) ldm_x4(af[i], paH + i * (16 * ROWB));
        ldm_x4(bf0[0], pbH);
        ldm_x4(bf0[1], pbH + 16 * ROWB);
        ldm_x4(bf1[0], pbH + TILEB);
        ldm_x4(bf1[1], pbH + TILEB + 16 * ROWB);

#pragma unroll
        for (int i = 0; i < 4; i++)
#pragma unroll
            for (int j = 0; j < 4; j++)
                mma16816(acc[i][j], af[i], &bf0[j >> 1][(j & 1) * 2]);
#pragma unroll
        for (int i = 0; i < 4; i++)
#pragma unroll
            for (int j = 0; j < 4; j++)
                mma16816(acc[i][j], af[i], &bf1[j >> 1][(j & 1) * 2]);
#pragma unroll
        for (int i = 0; i < 4; i++) ldm_x4(af[i], paH + TILEB + i * (16 * ROWB));
#pragma unroll
        for (int i = 0; i < 4; i++)
#pragma unroll
            for (int j = 0; j < 4; j++)
                mma16816(acc[i][j], af[i], &bf0[j >> 1][(j & 1) * 2]);
    }
}

__device__ __forceinline__ void gemm_mainloop(
    uint32_t sb, const __nv_bfloat16* const* srcs, int tid,
    int wm, int wn, uint32_t a_off, uint32_t b_off, float acc[4][4][4])
{
#pragma unroll
    for (int i = 0; i < 4; i++)
#pragma unroll
        for (int j = 0; j < 4; j++)
#pragma unroll
            for (int r = 0; r < 4; r++) acc[i][j][r] = 0.0f;

    load_chunk(sb, srcs, tid, 0);
    const int nchunks = GK / 32;
    for (int c = 0; c < nchunks; c++) {
        cpa_wait<0>();
        __syncthreads();
        if (c + 1 < nchunks)
            load_chunk(sb + ((c + 1) & 1) * STAGEB, srcs, tid, c + 1);
        compute_chunk(sb + (c & 1) * STAGEB, wm, wn, a_off, b_off, acc);
    }
}

// ---------------- fused QKV projection GEMM ----------------
// grid.x: 0..15 -> Q head, 16..23 -> K head, 24..31 -> V head (bf16 split out)
__global__ void __launch_bounds__(256) gemm_qkv()
{
    extern __shared__ char smem[];
    const uint32_t sb = smem_u32(smem);
    const int tid = threadIdx.x;
    const int lane = tid & 31;
    const int w = tid >> 5;
    const int wm = w >> 2;
    const int wn = w & 3;
    const int m0 = blockIdx.y * 128;
    const int xt = blockIdx.x;

    const __nv_bfloat16 *Bh_, *Bl_;
    float* Cf = 0;
    int head, heads;
    bool splitv = false;
    if (xt < 16) {
        Bh_ = g_wqh; Bl_ = g_wql; head = xt; heads = NH; Cf = g_q;
    } else if (xt < 24) {
        Bh_ = g_wkh; Bl_ = g_wkl; head = xt - 16; heads = NKV; Cf = g_k;
    } else {
        Bh_ = g_wvh; Bl_ = g_wvl; head = xt - 24; heads = NKV; splitv = true;
    }
    const int n0 = head * 128;

    const __nv_bfloat16* srcs[4] = {
        g_xh + (size_t)m0 * GK, g_xl + (size_t)m0 * GK,
        Bh_ + (size_t)n0 * GK, Bl_ + (size_t)n0 * GK};

    const uint32_t a_off = (uint32_t)(lane & 15) * ROWB + (uint32_t)(lane >> 4) * 16;
    const uint32_t b_off = (uint32_t)((lane & 7) + ((lane >> 4) << 3)) * ROWB +
                           (uint32_t)((lane >> 3) & 1) * 16;

    float acc[4][4][4];
    gemm_mainloop(sb, srcs, tid, wm, wn, a_off, b_off, acc);

    const int g = lane >> 2;
    const int tg = lane & 3;
#pragma unroll
    for (int i = 0; i < 4; i++) {
        const int mrow0 = m0 + wm * 64 + i * 16 + g;
#pragma unroll
        for (int j = 0; j < 4; j++) {
            const int col = wn * 32 + j * 8 + tg * 2;
#pragma unroll
            for (int h2 = 0; h2 < 2; h2++) {
                const int m = mrow0 + h2 * 8;
                const int b = m >> 11;
                const int t = m & (NT - 1);
                const float v0 = acc[i][j][h2 * 2];
                const float v1 = acc[i][j][h2 * 2 + 1];
                const size_t base = (((size_t)b * heads + head) * NT + t) * DHD + col;
                if (splitv) {
                    uint32_t h = packbf(v0, v1);
                    uint32_t lo = packbf(v0 - bflo(h), v1 - bfhi(h));
                    *(uint32_t*)(g_vbh + base) = h;
                    *(uint32_t*)(g_vbl + base) = lo;
                } else {
                    float2 v = {v0, v1};
                    *(float2*)(Cf + base) = v;
                }
            }
        }
    }
}

// ---------------- output projection GEMM (fp32 out, row-major) ----------------
__global__ void __launch_bounds__(256) gemm_oproj(float* __restrict__ C)
{
    extern __shared__ char smem[];
    const uint32_t sb = smem_u32(smem);
    const int tid = threadIdx.x;
    const int lane = tid & 31;
    const int w = tid >> 5;
    const int wm = w >> 2;
    const int wn = w & 3;
    const int m0 = blockIdx.y * 128;
    const int n0 = blockIdx.x * 128;

    const __nv_bfloat16* srcs[4] = {
        g_ch + (size_t)m0 * GK, g_cl + (size_t)m0 * GK,
        g_woh + (size_t)n0 * GK, g_wol + (size_t)n0 * GK};

    const uint32_t a_off = (uint32_t)(lane & 15) * ROWB + (uint32_t)(lane >> 4) * 16;
    const uint32_t b_off = (uint32_t)((lane & 7) + ((lane >> 4) << 3)) * ROWB +
                           (uint32_t)((lane >> 3) & 1) * 16;

    float acc[4][4][4];
    gemm_mainloop(sb, srcs, tid, wm, wn, a_off, b_off, acc);

    const int g = lane >> 2;
    const int tg = lane & 3;
#pragma unroll
    for (int i = 0; i < 4; i++) {
        const int mrow0 = m0 + wm * 64 + i * 16 + g;
#pragma unroll
        for (int j = 0; j < 4; j++) {
            const int col = n0 + wn * 32 + j * 8 + tg * 2;
#pragma unroll
            for (int h2 = 0; h2 < 2; h2++) {
                const int m = mrow0 + h2 * 8;
                float2 v = {acc[i][j][h2 * 2], acc[i][j][h2 * 2 + 1]};
                *(float2*)(C + (size_t)m * ND + col) = v;
            }
        }
    }
}

// ---------------- RoPE table ----------------
__global__ void rope_table_kernel() {
    const int t = blockIdx.x;
    const int fi = threadIdx.x;
    const float invf = (float)exp(-(double)fi * (13.815510557964274 / 64.0));
    const float arg = (float)t * invf;
    float s, c;
    sincosf(arg, &s, &c);
    g_cos[t * 64 + fi] = c;
    g_sin[t * 64 + fi] = s;
}

// ---------------- fused RMSNorm + RoPE + bf16 hi/lo split ----------------
__global__ void __launch_bounds__(256) normrope_kernel(
    const float* __restrict__ buf, __nv_bfloat16* __restrict__ oh,
    __nv_bfloat16* __restrict__ ol, const float* __restrict__ w)
{
    const int row = blockIdx.x * 8 + (threadIdx.x >> 5);
    const int lid = threadIdx.x & 31;
    const int t = row & (NT - 1);
    const float* p = buf + (size_t)row * DHD + lid * 4;

    float4 v = *(const float4*)p;
    float ss = v.x * v.x + v.y * v.y + v.z * v.z + v.w * v.w;
#pragma unroll
    for (int o = 16; o > 0; o >>= 1) ss += __shfl_xor_sync(0xffffffffu, ss, o);
    const float rn = rsqrtf(ss * (1.0f / 128.0f) + 1e-6f);

    float4 wv = *(const float4*)(w + lid * 4);
    float x0 = v.x * rn * wv.x, x1 = v.y * rn * wv.y;
    float x2 = v.z * rn * wv.z, x3 = v.w * rn * wv.w;

    const float p0 = __shfl_xor_sync(0xffffffffu, x0, 16);
    const float p1 = __shfl_xor_sync(0xffffffffu, x1, 16);
    const float p2 = __shfl_xor_sync(0xffffffffu, x2, 16);
    const float p3 = __shfl_xor_sync(0xffffffffu, x3, 16);

    const int fi0 = (lid & 15) * 4;
    float4 cv = *(const float4*)(g_cos + t * 64 + fi0);
    float4 sv = *(const float4*)(g_sin + t * 64 + fi0);
    const float sg = (lid < 16) ? -1.0f : 1.0f;

    float o0 = x0 * cv.x + sg * p0 * sv.x;
    float o1 = x1 * cv.y + sg * p1 * sv.y;
    float o2 = x2 * cv.z + sg * p2 * sv.z;
    float o3 = x3 * cv.w + sg * p3 * sv.w;

    uint32_t h0 = packbf(o0, o1), h1 = packbf(o2, o3);
    uint32_t l0 = packbf(o0 - bflo(h0), o1 - bfhi(h0));
    uint32_t l1 = packbf(o2 - bflo(h1), o3 - bfhi(h1));
    uint2 hv = {h0, h1}, lv = {l0, l1};
    ((uint2*)(oh + (size_t)row * DHD))[lid] = hv;
    ((uint2*)(ol + (size_t)row * DHD))[lid] = lv;
}

// ---------------- HMMA flash attention, causal, GQA ----------------
#define AROW   272
#define QTB    (128 * AROW)
#define KTB    (64 * AROW)
#define KVSTG  (4 * KTB)
#define ASMEM  (2 * QTB + 2 * KVSTG)   // 208896

__global__ void __launch_bounds__(256) attn_mma_kernel()
{
    extern __shared__ char smem[];
    const uint32_t sb = smem_u32(smem);
    const int tid = threadIdx.x;
    const int lane = tid & 31;
    const int w = tid >> 5;
    const int bh = blockIdx.x;              // head-fastest: waves mix tile sizes
    const int b = bh >> 4;
    const int hq = bh & 15;
    const int hk = hq >> 1;
    const int qt = (NT / 128 - 1) - blockIdx.y;  // largest tiles first
    const int q0 = qt * 128;
    const int last = 2 * qt + 1;

    const __nv_bfloat16* Qhg = g_qh + (((size_t)b * NH + hq) * NT + q0) * DHD;
    const __nv_bfloat16* Qlg = g_ql + (((size_t)b * NH + hq) * NT + q0) * DHD;
    const __nv_bfloat16* Khg = g_kbh + ((size_t)b * NKV + hk) * NT * DHD;
    const __nv_bfloat16* Klg = g_kbl + ((size_t)b * NKV + hk) * NT * DHD;
    const __nv_bfloat16* Vhg = g_vbh + ((size_t)b * NKV + hk) * NT * DHD;
    const __nv_bfloat16* Vlg = g_vbl + ((size_t)b * NKV + hk) * NT * DHD;

    const uint32_t sQh = sb, sQl = sb + QTB;
    const uint32_t sKV0 = sb + 2 * QTB;

#pragma unroll
    for (int i = 0; i < 8; i++) {
        const int idx = tid + i * 256;
        const int r = idx >> 4, ch = idx & 15;
        cpa16(sQh + r * AROW + ch * 16, Qhg + (size_t)r * DHD + ch * 8);
        cpa16(sQl + r * AROW + ch * 16, Qlg + (size_t)r * DHD + ch * 8);
    }
    cpa_commit();

    auto load_kv = [&](int stage, int jt) {
        const uint32_t base = sKV0 + stage * KVSTG;
        const size_t off = (size_t)jt * 64 * DHD;
        const __nv_bfloat16* srcs[4] = {Khg + off, Klg + off, Vhg + off, Vlg + off};
#pragma unroll
        for (int t = 0; t < 4; t++)
#pragma unroll
            for (int i = 0; i < 4; i++) {
                const int idx = tid + i * 256;
                const int r = idx >> 4, ch = idx & 15;
                cpa16(base + t * KTB + r * AROW + ch * 16,
                      srcs[t] + (size_t)r * DHD + ch * 8);
            }
        cpa_commit();
    };
    load_kv(0, 0);

    cpa_wait<1>();
    __syncthreads();

    const uint32_t a_off = (uint32_t)(lane & 15) * AROW + (uint32_t)(lane >> 4) * 16;
    const uint32_t kb_off = (uint32_t)((lane & 7) + ((lane >> 4) << 3)) * AROW +
                            (uint32_t)((lane >> 3) & 1) * 16;
    const uint32_t vb_off = (uint32_t)((lane & 7) + (((lane >> 3) & 1) << 3)) * AROW +
                            (uint32_t)(lane >> 4) * 16;

    uint32_t qh[8][4];
#pragma unroll
    for (int c = 0; c < 8; c++) ldm_x4(qh[c], sQh + w * 16 * AROW + a_off + c * 32);

    float oacc[16][4];
#pragma unroll
    for (int n = 0; n < 16; n++)
#pragma unroll
        for (int r = 0; r < 4; r++) oacc[n][r] = 0.0f;
    float m0 = -1e30f, m1 = -1e30f, l0 = 0.0f, l1 = 0.0f;

    const float CEXP = 0.12751740493262602f;  // (1/sqrt(128)) * log2(e)
    const int r0g = q0 + w * 16 + (lane >> 2);
    const int r1g = r0g + 8;

    for (int jt = 0; jt <= last; jt++) {
        __syncthreads();
        if (jt < last) {
            load_kv((jt + 1) & 1, jt + 1);
            cpa_wait<1>();
        } else {
            cpa_wait<0>();
        }
        __syncthreads();

        const uint32_t kb = sKV0 + (jt & 1) * KVSTG;

        float s[8][4];
#pragma unroll
        for (int j = 0; j < 8; j++)
#pragma unroll
            for (int r = 0; r < 4; r++) s[j][r] = 0.0f;

#pragma unroll
        for (int c = 0; c < 8; c++) {
            uint32_t kh[4][4], kl[4][4], ql[4];
#pragma unroll
            for (int m = 0; m < 4; m++)
                ldm_x4(kh[m], kb + kb_off + m * (16 * AROW) + c * 32);
#pragma unroll
            for (int m = 0; m < 4; m++)
                ldm_x4(kl[m], kb + KTB + kb_off + m * (16 * AROW) + c * 32);
            ldm_x4(ql, sQl + w * 16 * AROW + a_off + c * 32);
#pragma unroll
            for (int j = 0; j < 8; j++) {
                mma16816(s[j], qh[c], &kh[j >> 1][(j & 1) * 2]);
                mma16816(s[j], qh[c], &kl[j >> 1][(j & 1) * 2]);
                mma16816(s[j], ql, &kh[j >> 1][(j & 1) * 2]);
            }
        }

        const int k0 = jt * 64;
        if (k0 + 63 > q0 + w * 16) {
#pragma unroll
            for (int j = 0; j < 8; j++) {
                const int col0 = k0 + j * 8 + (lane & 3) * 2;
                if (col0 > r0g) s[j][0] = -1e30f;
                if (col0 + 1 > r0g) s[j][1] = -1e30f;
                if (col0 > r1g) s[j][2] = -1e30f;
                if (col0 + 1 > r1g) s[j][3] = -1e30f;
            }
        }
        float rmax0 = -1e30f, rmax1 = -1e30f;
#pragma unroll
        for (int j = 0; j < 8; j++) {
            rmax0 = fmaxf(rmax0, fmaxf(s[j][0], s[j][1]));
            rmax1 = fmaxf(rmax1, fmaxf(s[j][2], s[j][3]));
        }
        rmax0 = fmaxf(rmax0, __shfl_xor_sync(0xffffffffu, rmax0, 1));
        rmax0 = fmaxf(rmax0, __shfl_xor_sync(0xffffffffu, rmax0, 2));
        rmax1 = fmaxf(rmax1, __shfl_xor_sync(0xffffffffu, rmax1, 1));
        rmax1 = fmaxf(rmax1, __shfl_xor_sync(0xffffffffu, rmax1, 2));

        const float mn0 = fmaxf(m0, rmax0);
        const float mn1 = fmaxf(m1, rmax1);
        const float al0 = ex2f((m0 - mn0) * CEXP);
        const float al1 = ex2f((m1 - mn1) * CEXP);
        m0 = mn0;
        m1 = mn1;

        float sum0 = 0.0f, sum1 = 0.0f;
#pragma unroll
        for (int j = 0; j < 8; j++) {
            s[j][0] = ex2f((s[j][0] - mn0) * CEXP);
            s[j][1] = ex2f((s[j][1] - mn0) * CEXP);
            s[j][2] = ex2f((s[j][2] - mn1) * CEXP);
            s[j][3] = ex2f((s[j][3] - mn1) * CEXP);
            sum0 += s[j][0] + s[j][1];
            sum1 += s[j][2] + s[j][3];
        }
        sum0 += __shfl_xor_sync(0xffffffffu, sum0, 1);
        sum0 += __shfl_xor_sync(0xffffffffu, sum0, 2);
        sum1 += __shfl_xor_sync(0xffffffffu, sum1, 1);
        sum1 += __shfl_xor_sync(0xffffffffu, sum1, 2);
        l0 = l0 * al0 + sum0;
        l1 = l1 * al1 + sum1;

#pragma unroll
        for (int n = 0; n < 16; n++) {
            oacc[n][0] *= al0;
            oacc[n][1] *= al0;
            oacc[n][2] *= al1;
            oacc[n][3] *= al1;
        }

        const uint32_t vbh = kb + 2 * KTB;
        const uint32_t vbl = kb + 3 * KTB;
#pragma unroll
        for (int kt = 0; kt < 4; kt++) {
            const int j0 = 2 * kt, j1 = 2 * kt + 1;
            uint32_t ph[4], pl[4];
            ph[0] = packbf(s[j0][0], s[j0][1]);
            ph[1] = packbf(s[j0][2], s[j0][3]);
            ph[2] = packbf(s[j1][0], s[j1][1]);
            ph[3] = packbf(s[j1][2], s[j1][3]);
            pl[0] = packbf(s[j0][0] - bflo(ph[0]), s[j0][1] - bfhi(ph[0]));
            pl[1] = packbf(s[j0][2] - bflo(ph[1]), s[j0][3] - bfhi(ph[1]));
            pl[2] = packbf(s[j1][0] - bflo(ph[2]), s[j1][1] - bfhi(ph[2]));
            pl[3] = packbf(s[j1][2] - bflo(ph[3]), s[j1][3] - bfhi(ph[3]));
#pragma unroll
            for (int d = 0; d < 8; d++) {
                uint32_t vh[4], vl[4];
                ldm_x4_t(vh, vbh + vb_off + kt * (16 * AROW) + d * 32);
                ldm_x4_t(vl, vbl + vb_off + kt * (16 * AROW) + d * 32);
                mma16816(oacc[2 * d], ph, vh);
                mma16816(oacc[2 * d + 1], ph, vh + 2);
                mma16816(oacc[2 * d], pl, vh);
                mma16816(oacc[2 * d + 1], pl, vh + 2);
                mma16816(oacc[2 * d], ph, vl);
                mma16816(oacc[2 * d + 1], ph, vl + 2);
            }
        }
    }

    const float inv0 = 1.0f / l0;
    const float inv1 = 1.0f / l1;
    const size_t rowA = ((size_t)b * NT + r0g) * (NH * DHD) + hq * DHD;
    const size_t rowB = ((size_t)b * NT + r1g) * (NH * DHD) + hq * DHD;
#pragma unroll
    for (int n = 0; n < 16; n++) {
        const int col = n * 8 + (lane & 3) * 2;
        float v0 = oacc[n][0] * inv0, v1 = oacc[n][1] * inv0;
        uint32_t h = packbf(v0, v1);
        uint32_t lo = packbf(v0 - bflo(h), v1 - bfhi(h));
        *(uint32_t*)(g_ch + rowA + col) = h;
        *(uint32_t*)(g_cl + rowA + col) = lo;
        float v2 = oacc[n][2] * inv1, v3 = oacc[n][3] * inv1;
        uint32_t h2 = packbf(v2, v3);
        uint32_t lo2 = packbf(v2 - bflo(h2), v3 - bfhi(h2));
        *(uint32_t*)(g_ch + rowB + col) = h2;
        *(uint32_t*)(g_cl + rowB + col) = lo2;
    }
}

// ---------------------------------------------------------------------------
extern "C" void kernel_launch(void* const* d_in, const int* in_sizes, int n_in,
                              void* d_out, int out_size)
{
    const float* x   = (const float*)d_in[0];
    const float* wq  = (const float*)d_in[1];
    const float* wk  = (const float*)d_in[2];
    const float* wv  = (const float*)d_in[3];
    const float* wo  = (const float*)d_in[4];
    const float* qnw = (const float*)d_in[5];
    const float* knw = (const float*)d_in[6];
    float* out = (float*)d_out;

    float *qp, *kp;
    __nv_bfloat16 *xh, *xl, *wqh, *wql, *wkh, *wkl, *wvh, *wvl, *woh, *wol;
    __nv_bfloat16 *qhp, *qlp, *kbh, *kbl;
    cudaGetSymbolAddress((void**)&qp, g_q);
    cudaGetSymbolAddress((void**)&kp, g_k);
    cudaGetSymbolAddress((void**)&xh, g_xh);
    cudaGetSymbolAddress((void**)&xl, g_xl);
    cudaGetSymbolAddress((void**)&wqh, g_wqh);
    cudaGetSymbolAddress((void**)&wql, g_wql);
    cudaGetSymbolAddress((void**)&wkh, g_wkh);
    cudaGetSymbolAddress((void**)&wkl, g_wkl);
    cudaGetSymbolAddress((void**)&wvh, g_wvh);
    cudaGetSymbolAddress((void**)&wvl, g_wvl);
    cudaGetSymbolAddress((void**)&woh, g_woh);
    cudaGetSymbolAddress((void**)&wol, g_wol);
    cudaGetSymbolAddress((void**)&qhp, g_qh);
    cudaGetSymbolAddress((void**)&qlp, g_ql);
    cudaGetSymbolAddress((void**)&kbh, g_kbh);
    cudaGetSymbolAddress((void**)&kbl, g_kbl);

    cudaFuncSetAttribute(gemm_qkv,
                         cudaFuncAttributeMaxDynamicSharedMemorySize, GSMEM);
    cudaFuncSetAttribute(gemm_oproj,
                         cudaFuncAttributeMaxDynamicSharedMemorySize, GSMEM);
    cudaFuncSetAttribute(attn_mma_kernel,
                         cudaFuncAttributeMaxDynamicSharedMemorySize, ASMEM);

    const int M = NB * NT;  // 4096

    // hi/lo splits (launches 1-5)
    split_kernel<<<(M * ND / 4 + 255) / 256, 256>>>(x, xh, xl, M * ND / 4);
    split_kernel<<<(ND * ND / 4 + 255) / 256, 256>>>(wq, wqh, wql, ND * ND / 4);
    split_kernel<<<(1024 * ND / 4 + 255) / 256, 256>>>(wk, wkh, wkl, 1024 * ND / 4);
    split_kernel<<<(1024 * ND / 4 + 255) / 256, 256>>>(wv, wvh, wvl, 1024 * ND / 4);
    split_kernel<<<(ND * ND / 4 + 255) / 256, 256>>>(wo, woh, wol, ND * ND / 4);

    // launch 6 (ncu -s 5 -c 1 captures this): fused QKV projections
    gemm_qkv<<<dim3(32, M / 128), 256, GSMEM>>>();

    rope_table_kernel<<<NT, 64>>>();
    normrope_kernel<<<NB * NH * NT / 8, 256>>>(qp, qhp, qlp, qnw);
    normrope_kernel<<<NB * NKV * NT / 8, 256>>>(kp, kbh, kbl, knw);

    // attention: grid (heads, tiles) — every wave mixes tile sizes
    attn_mma_kernel<<<dim3(NB * NH, NT / 128), 256, ASMEM>>>();

    // output projection
    gemm_oproj<<<dim3(ND / 128, M / 128), 256, GSMEM>>>(out);
}